// round 15
// baseline (speedup 1.0000x reference)
#include <cuda_runtime.h>
#include <cuda_bf16.h>
#include <cstdint>

// ---------------------------------------------------------------------------
// Arch feature gate: tcgen05 only on arch/family-specific sm_10x targets.
// ---------------------------------------------------------------------------
#if defined(__CUDA_ARCH__)
#  if defined(__CUDA_ARCH_FEAT_SM103_ALL) || defined(__CUDA_ARCH_FEAT_SM100_ALL)
#    define HAS_TC 1
#  elif defined(__CUDA_ARCH_SPECIFIC__) && (__CUDA_ARCH_SPECIFIC__ == 1030 || __CUDA_ARCH_SPECIFIC__ == 1000)
#    define HAS_TC 1
#  elif defined(__CUDA_ARCH_FAMILY_SPECIFIC__) && (__CUDA_ARCH_FAMILY_SPECIFIC__ == 1030 || __CUDA_ARCH_FAMILY_SPECIFIC__ == 1000)
#    define HAS_TC 1
#  else
#    define HAS_TC 0
#  endif
#else
#  define HAS_TC 0
#endif

#define B_ 8
#define L_ 512
#define D_ 768
#define W_ 12

constexpr int NROW  = B_ * L_;       // 4096
constexpr int MROW2 = NROW * W_;     // 49152
constexpr int CH    = 64;            // K-chunk (bf16) = 128B rows (SW128)
constexpr int NCH   = D_ / CH;       // 12
constexpr int NT    = 192;           // N per CTA (one MMA, N=192)

// ---- SMEM map (tc kernels): 2-stage, N=192 tiles (proven 164864B) ----
constexpr int SM_TMEM  = 0;
constexpr int SM_MBAR  = 8;
constexpr int SM_BIAS  = 256;                  // 192 floats (proj)
constexpr int SM_TILES = 1024;
constexpr int TILE_A   = 128 * 128;            // 16 KB  (A: 128 rows x 128B)
constexpr int TILE_BN  = NT * 128;             // 24576 (B: 192 rows x 128B)
constexpr int OFF_AH   = 0;
constexpr int OFF_AL   = TILE_A;
constexpr int OFF_BH   = 2 * TILE_A;
constexpr int OFF_BL   = 2 * TILE_A + TILE_BN;
constexpr int BUF_B    = 2 * TILE_A + 2 * TILE_BN;   // 81920
constexpr int SMEM_SZ  = SM_TILES + 2 * BUF_B;       // 164864 (< hang zone)
constexpr int BROW_B   = 784;                  // bounce row pitch (768B + 16B pad)
// conv: half-tile bounce (64 rows) confined to buffer-1 region so a prefetch
// into buffer 0 can be in flight during the epilogue.
constexpr int BOUNCE_OFF = SM_TILES + BUF_B;   // == buffer 1 start; 64*784 <= 81920

// idesc kind::f16 : dtype=F32, a=BF16, b=BF16, N=192, M=128
constexpr uint32_t IDESC =
    (1u << 4) | (1u << 7) | (1u << 10) | ((uint32_t)(NT / 8) << 17) | ((128u / 16) << 24);

// ---- scratch ----
__device__ __nv_bfloat16 g_xhi[(size_t)NROW * D_],   g_xlo[(size_t)NROW * D_];
__device__ __nv_bfloat16 g_whi[(size_t)W_ * D_ * D_], g_wlo[(size_t)W_ * D_ * D_]; // [k][o][c]
__device__ __nv_bfloat16 g_phi[(size_t)D_ * D_],     g_plo[(size_t)D_ * D_];       // [o][d]
__device__ __nv_bfloat16 g_hhi[(size_t)MROW2 * D_],  g_hlo[(size_t)MROW2 * D_];
// SIMT fallback scratch
__device__ float g_Wt[(size_t)W_ * D_ * D_];
__device__ float g_Pt[(size_t)D_ * D_];
__device__ float g_H [(size_t)MROW2 * D_];

// ===========================================================================
// helpers
// ===========================================================================
__device__ __forceinline__ uint32_t smem_u32(const void* p) {
    uint32_t a;
    asm("{ .reg .u64 t; cvta.to.shared.u64 t, %1; cvt.u32.u64 %0, t; }" : "=r"(a) : "l"(p));
    return a;
}
__device__ __forceinline__ void split2(float v, __nv_bfloat16& hi, __nv_bfloat16& lo) {
    hi = __float2bfloat16(v);
    lo = __float2bfloat16(v - __bfloat162float(hi));
}

#if HAS_TC
__device__ __forceinline__ uint32_t elect_one() {
    uint32_t p;
    asm volatile("{ .reg .pred p; elect.sync _|p, 0xFFFFFFFF; selp.b32 %0, 1, 0, p; }" : "=r"(p));
    return p;
}
__device__ __forceinline__ void mbar_init(uint32_t m, uint32_t cnt) {
    asm volatile("mbarrier.init.shared.b64 [%0], %1;" :: "r"(m), "r"(cnt) : "memory");
}
__device__ __forceinline__ void mbar_inval(uint32_t m) {
    asm volatile("mbarrier.inval.shared.b64 [%0];" :: "r"(m) : "memory");
}
__device__ __forceinline__ void mbar_wait(uint32_t m, uint32_t parity) {
    asm volatile(
        "{\n\t.reg .pred P;\n\t"
        "WL_%=:\n\t"
        "mbarrier.try_wait.parity.acquire.cta.shared::cta.b64 P, [%0], %1, 0x989680;\n\t"
        "@P bra.uni WD_%=;\n\t"
        "bra.uni WL_%=;\n\t"
        "WD_%=:\n\t}"
        :: "r"(m), "r"(parity) : "memory");
}
__device__ __forceinline__ void tmem_alloc(uint32_t smem_dst, uint32_t ncols) {
    asm volatile("tcgen05.alloc.cta_group::1.sync.aligned.shared::cta.b32 [%0], %1;"
                 :: "r"(smem_dst), "r"(ncols) : "memory");
}
__device__ __forceinline__ void tmem_dealloc(uint32_t tmem, uint32_t ncols) {
    asm volatile("tcgen05.relinquish_alloc_permit.cta_group::1.sync.aligned;");
    asm volatile("tcgen05.dealloc.cta_group::1.sync.aligned.b32 %0, %1;" :: "r"(tmem), "r"(ncols));
}
__device__ __forceinline__ void mma_commit(uint32_t mbar) {
    asm volatile("tcgen05.commit.cta_group::1.mbarrier::arrive::one.shared::cluster.b64 [%0];"
                 :: "r"(mbar) : "memory");
}
__device__ __forceinline__ void fence_after()  { asm volatile("tcgen05.fence::after_thread_sync;"  ::: "memory"); }
__device__ __forceinline__ void fence_before() { asm volatile("tcgen05.fence::before_thread_sync;" ::: "memory"); }
__device__ __forceinline__ void wait_ld()      { asm volatile("tcgen05.wait::ld.sync.aligned;"     ::: "memory"); }
__device__ __forceinline__ void fence_async()  { asm volatile("fence.proxy.async.shared::cta;"     ::: "memory"); }

// cp.async 16B copy (sm_80+): plain and zero-fill-predicated forms.
__device__ __forceinline__ void cp16(uint32_t dst, const void* src) {
    asm volatile("cp.async.cg.shared.global [%0], [%1], 16;"
                 :: "r"(dst), "l"(src) : "memory");
}
__device__ __forceinline__ void cp16z(uint32_t dst, const void* src, int src_size) {
    asm volatile("cp.async.cg.shared.global [%0], [%1], 16, %2;"
                 :: "r"(dst), "l"(src), "r"(src_size) : "memory");
}
__device__ __forceinline__ void cp_commit() {
    asm volatile("cp.async.commit_group;" ::: "memory");
}
__device__ __forceinline__ void cp_wait0() {
    asm volatile("cp.async.wait_group 0;" ::: "memory");
}
__device__ __forceinline__ void cp_wait1() {
    asm volatile("cp.async.wait_group 1;" ::: "memory");
}

__device__ __forceinline__ void mma_f16_ss(uint32_t d_tmem, uint64_t a_desc, uint64_t b_desc,
                                           uint32_t idesc, bool acc) {
    uint32_t en = acc ? 1u : 0u;
    uint32_t z = 0;
    asm volatile(
        "{\n\t.reg .pred p;\n\tsetp.ne.u32 p, %5, 0;\n\t"
        "tcgen05.mma.cta_group::1.kind::f16 [%0], %1, %2, %3, {%4, %4, %4, %4}, p;\n\t}"
        :: "r"(d_tmem), "l"(a_desc), "l"(b_desc), "r"(idesc), "r"(z), "r"(en) : "memory");
}
__device__ __forceinline__ uint64_t make_desc(uint32_t addr) {
    constexpr uint64_t BASE =
        (uint64_t(2) << 61) | (uint64_t(1) << 46) | (uint64_t(64) << 32) | (uint64_t(1) << 16);
    return BASE | ((uint64_t)(addr >> 4) & 0x3FFF);
}
#define LDTM_X32(r, a)                                                              \
    asm volatile("tcgen05.ld.sync.aligned.32x32b.x32.b32 "                          \
        "{%0, %1, %2, %3, %4, %5, %6, %7, %8, %9, %10, %11, %12, %13, %14, %15, "   \
        " %16, %17, %18, %19, %20, %21, %22, %23, %24, %25, %26, %27, %28, %29, %30, %31}, [%32];" \
        : "=r"((r)[0]), "=r"((r)[1]), "=r"((r)[2]), "=r"((r)[3]),                   \
          "=r"((r)[4]), "=r"((r)[5]), "=r"((r)[6]), "=r"((r)[7]),                   \
          "=r"((r)[8]), "=r"((r)[9]), "=r"((r)[10]), "=r"((r)[11]),                 \
          "=r"((r)[12]), "=r"((r)[13]), "=r"((r)[14]), "=r"((r)[15]),               \
          "=r"((r)[16]), "=r"((r)[17]), "=r"((r)[18]), "=r"((r)[19]),               \
          "=r"((r)[20]), "=r"((r)[21]), "=r"((r)[22]), "=r"((r)[23]),               \
          "=r"((r)[24]), "=r"((r)[25]), "=r"((r)[26]), "=r"((r)[27]),               \
          "=r"((r)[28]), "=r"((r)[29]), "=r"((r)[30]), "=r"((r)[31])                \
        : "r"(a))
#endif // HAS_TC

// ===========================================================================
// tc-path prep kernels
// ===========================================================================
__global__ void split_x_kernel(const float* __restrict__ x) {
#if HAS_TC
    int g = blockIdx.x * 256 + threadIdx.x;
    if (g >= NROW * D_) return;
    __nv_bfloat16 h, l;
    split2(x[g], h, l);
    g_xhi[g] = h; g_xlo[g] = l;
#endif
}
__global__ void split_w_kernel(const float* __restrict__ cw) {  // [o][c][k] -> [k][o][c]
#if HAS_TC
    int g = blockIdx.x * 256 + threadIdx.x;
    if (g >= D_ * D_) return;
    int c = g % D_, o = g / D_;
    const float* src = cw + ((size_t)o * D_ + c) * W_;
#pragma unroll
    for (int k = 0; k < W_; k++) {
        __nv_bfloat16 h, l;
        split2(src[k], h, l);
        size_t dst = ((size_t)k * D_ + o) * D_ + c;
        g_whi[dst] = h; g_wlo[dst] = l;
    }
#endif
}
__global__ void split_p_kernel(const float* __restrict__ pw) {
#if HAS_TC
    int g = blockIdx.x * 256 + threadIdx.x;
    if (g >= D_ * D_) return;
    __nv_bfloat16 h, l;
    split2(pw[g], h, l);
    g_phi[g] = h; g_plo[g] = l;
#endif
}

// ===========================================================================
// tc Kernel 1: taps GEMM (M=128 x N=192 per CTA), cumsum in TMEM.
// 256 threads. Uniform one-chunk-ahead prefetch INCLUDING across taps:
// the epilogue bounce lives in buffer 1 only (two 64-row passes) so the
// prefetch of next tap's chunk 0 (always buffer 0) stays in flight under it.
// ===========================================================================
__global__ __launch_bounds__(256, 1) void conv_mma_kernel() {
#if HAS_TC
    extern __shared__ char smem[];
    const uint32_t sbase = smem_u32(smem);
    const int tid = threadIdx.x;
    const int wid = tid >> 5, lid = tid & 31;

    if (wid == 0) tmem_alloc(sbase + SM_TMEM, 256);
    if (tid == 0) mbar_init(sbase + SM_MBAR, 1);
    __syncthreads();
    uint32_t tmem;
    asm volatile("ld.shared.b32 %0, [%1];" : "=r"(tmem) : "r"(sbase + SM_TMEM));

    const int n0 = blockIdx.x * NT;
    const int m0 = blockIdx.y * 128;
    const int bb = m0 / L_;
    const int l0 = m0 % L_;

    // fill chunk (k, kc) into stage buffer b; one commit group per call
    auto fill_chunk = [&](int k, int kc, int b) {
        const int kc0 = kc * CH;
        const uint32_t bufu = sbase + SM_TILES + b * BUF_B;
#pragma unroll
        for (int it = 0; it < 4; it++) {                   // A tiles (shifted rows)
            int idx = it * 256 + tid;
            int rowt = idx >> 3, c16 = idx & 7;
            int t = l0 + rowt + k;
            int tcl = t < L_ ? t : (L_ - 1);
            int pr  = t < L_ ? 16 : 0;
            size_t off = ((size_t)(bb * L_ + tcl)) * D_ + kc0;
            int bo = rowt * 128 + c16 * 16;
            int sw = bo ^ ((bo >> 3) & 0x70);
            cp16z(bufu + OFF_AH + sw, (const char*)(g_xhi + off) + c16 * 16, pr);
            cp16z(bufu + OFF_AL + sw, (const char*)(g_xlo + off) + c16 * 16, pr);
        }
#pragma unroll
        for (int it = 0; it < 6; it++) {                   // B tiles (192 rows, tap k)
            int idx = it * 256 + tid;
            int rowt = idx >> 3, c16 = idx & 7;
            size_t off = ((size_t)k * D_ + (n0 + rowt)) * D_ + kc0;
            int bo = rowt * 128 + c16 * 16;
            int sw = bo ^ ((bo >> 3) & 0x70);
            cp16(bufu + OFF_BH + sw, (const char*)(g_whi + off) + c16 * 16);
            cp16(bufu + OFF_BL + sw, (const char*)(g_wlo + off) + c16 * 16);
        }
        cp_commit();
    };

    int cc = 0, wc = 0;
    fill_chunk(0, 0, 0);                                   // global prologue
    for (int k = 0; k < W_; k++) {
        for (int kc = 0; kc < NCH; kc++) {
            const bool last = (k == W_ - 1) && (kc == NCH - 1);
            if (!last) {
                // next chunk (wraps to (k+1, 0) at tap end); its buffer
                // (cc+1)&1 was last read by MMA(cc-1) -> wait that MMA
                while (wc < cc) { mbar_wait(sbase + SM_MBAR, wc & 1); wc++; }
                int nk  = (kc < NCH - 1) ? k : k + 1;
                int nkc = (kc < NCH - 1) ? kc + 1 : 0;
                fill_chunk(nk, nkc, (cc + 1) & 1);
                cp_wait1();                                 // fill(cc) complete
            } else {
                cp_wait0();
            }
            fence_async();
            __syncthreads();
            if (wid == 0 && elect_one()) {
                uint32_t b0 = sbase + SM_TILES + (cc & 1) * BUF_B;
                uint64_t dAh = make_desc(b0 + OFF_AH);
                uint64_t dAl = make_desc(b0 + OFF_AL);
                uint64_t dBh = make_desc(b0 + OFF_BH);
                uint64_t dBl = make_desc(b0 + OFF_BL);
                bool first = (cc == 0);
#pragma unroll
                for (int ks = 0; ks < 4; ks++)
                    mma_f16_ss(tmem, dAh + ks * 2, dBh + ks * 2, IDESC, !(first && ks == 0));
#pragma unroll
                for (int ks = 0; ks < 4; ks++)
                    mma_f16_ss(tmem, dAh + ks * 2, dBl + ks * 2, IDESC, true);
#pragma unroll
                for (int ks = 0; ks < 4; ks++)
                    mma_f16_ss(tmem, dAl + ks * 2, dBh + ks * 2, IDESC, true);
                mma_commit(sbase + SM_MBAR);
            }
            cc++;
        }
        while (wc < cc) { mbar_wait(sbase + SM_MBAR, wc & 1); wc++; }   // drain tap
        __syncthreads();
        fence_after();
        // ---- epilogue: two 64-row passes; bounce confined to buffer-1 region
        //      (prefetch of next tap's chunk 0 is in flight in buffer 0). ----
#pragma unroll
        for (int pass = 0; pass < 2; pass++) {
            if ((wid >> 1) == pass) {   // pass0: warps 0,1; pass1: warps 2,3
                float* brow = reinterpret_cast<float*>(
                    smem + BOUNCE_OFF + ((wid & 1) * 32 + lid) * BROW_B);
                uint32_t r0[32], r1[32];
#pragma unroll
                for (int g = 0; g < 3; g++) {
                    LDTM_X32(r0, tmem + (2 * g) * 32);
                    LDTM_X32(r1, tmem + (2 * g + 1) * 32);
                    wait_ld();
#pragma unroll
                    for (int j = 0; j < 32; j++)
                        brow[2 * g * 32 + j]       = fmaxf(__uint_as_float(r0[j]), 0.f);
#pragma unroll
                    for (int j = 0; j < 32; j++)
                        brow[(2 * g + 1) * 32 + j] = fmaxf(__uint_as_float(r1[j]), 0.f);
                }
            }
            __syncthreads();
            // store 64 rows (global rows m0 + pass*64 + rloc), all 8 warps
#pragma unroll
            for (int p = 0; p < 8; p++) {                  // cols 0..127
                int rloc = p * 8 + wid;
                float4 v = *reinterpret_cast<const float4*>(
                    smem + BOUNCE_OFF + rloc * BROW_B + lid * 16);
                __nv_bfloat16 h0, q0, h1, q1, h2, q2, h3, q3;
                split2(v.x, h0, q0); split2(v.y, h1, q1);
                split2(v.z, h2, q2); split2(v.w, h3, q3);
                __nv_bfloat162 ph0, ph1, pl0, pl1;
                ph0.x = h0; ph0.y = h1; ph1.x = h2; ph1.y = h3;
                pl0.x = q0; pl0.y = q1; pl1.x = q2; pl1.y = q3;
                size_t base = ((size_t)(m0 + pass * 64 + rloc) * W_ + k) * D_ + n0 + lid * 4;
                uint2 uh = make_uint2(*reinterpret_cast<uint32_t*>(&ph0),
                                      *reinterpret_cast<uint32_t*>(&ph1));
                uint2 ul = make_uint2(*reinterpret_cast<uint32_t*>(&pl0),
                                      *reinterpret_cast<uint32_t*>(&pl1));
                *reinterpret_cast<uint2*>(g_hhi + base) = uh;
                *reinterpret_cast<uint2*>(g_hlo + base) = ul;
            }
#pragma unroll
            for (int p = 0; p < 4; p++) {                  // cols 128..191
                int rloc = p * 16 + wid * 2 + (lid >> 4);
                int ll = lid & 15;
                float4 v = *reinterpret_cast<const float4*>(
                    smem + BOUNCE_OFF + rloc * BROW_B + 512 + ll * 16);
                __nv_bfloat16 h0, q0, h1, q1, h2, q2, h3, q3;
                split2(v.x, h0, q0); split2(v.y, h1, q1);
                split2(v.z, h2, q2); split2(v.w, h3, q3);
                __nv_bfloat162 ph0, ph1, pl0, pl1;
                ph0.x = h0; ph0.y = h1; ph1.x = h2; ph1.y = h3;
                pl0.x = q0; pl0.y = q1; pl1.x = q2; pl1.y = q3;
                size_t base = ((size_t)(m0 + pass * 64 + rloc) * W_ + k) * D_ + n0 + 128 + ll * 4;
                uint2 uh = make_uint2(*reinterpret_cast<uint32_t*>(&ph0),
                                      *reinterpret_cast<uint32_t*>(&ph1));
                uint2 ul = make_uint2(*reinterpret_cast<uint32_t*>(&pl0),
                                      *reinterpret_cast<uint32_t*>(&pl1));
                *reinterpret_cast<uint2*>(g_hhi + base) = uh;
                *reinterpret_cast<uint2*>(g_hlo + base) = ul;
            }
            __syncthreads();
        }
        fence_before();
        __syncthreads();
    }
    __syncthreads();
    if (tid == 0) mbar_inval(sbase + SM_MBAR);
    __syncthreads();
    if (wid == 0) tmem_dealloc(tmem, 256);
#endif
}

// ===========================================================================
// tc Kernel 2: out = H @ projT + bias (M=128 x N=192 per CTA). 256 threads.
// Byte-identical to R14.
// ===========================================================================
__global__ __launch_bounds__(256, 1) void proj_mma_kernel(const float* __restrict__ proj_b,
                                                          float* __restrict__ out) {
#if HAS_TC
    extern __shared__ char smem[];
    const uint32_t sbase = smem_u32(smem);
    const int tid = threadIdx.x;
    const int wid = tid >> 5, lid = tid & 31;

    if (wid == 0) tmem_alloc(sbase + SM_TMEM, 256);
    if (tid == 0) mbar_init(sbase + SM_MBAR, 1);
    const int n0 = blockIdx.x * NT;
    const int m0 = blockIdx.y * 128;
    if (tid < 192) reinterpret_cast<float*>(smem + SM_BIAS)[tid] = proj_b[n0 + tid];
    __syncthreads();
    uint32_t tmem;
    asm volatile("ld.shared.b32 %0, [%1];" : "=r"(tmem) : "r"(sbase + SM_TMEM));

    auto fill_chunk = [&](int kc, int b) {
        const int kc0 = kc * CH;
        const uint32_t bufu = sbase + SM_TILES + b * BUF_B;
#pragma unroll
        for (int it = 0; it < 4; it++) {
            int idx = it * 256 + tid;
            int rowt = idx >> 3, c16 = idx & 7;
            size_t off = (size_t)(m0 + rowt) * D_ + kc0;
            int bo = rowt * 128 + c16 * 16;
            int sw = bo ^ ((bo >> 3) & 0x70);
            cp16(bufu + OFF_AH + sw, (const char*)(g_hhi + off) + c16 * 16);
            cp16(bufu + OFF_AL + sw, (const char*)(g_hlo + off) + c16 * 16);
        }
#pragma unroll
        for (int it = 0; it < 6; it++) {
            int idx = it * 256 + tid;
            int rowt = idx >> 3, c16 = idx & 7;
            size_t off = (size_t)(n0 + rowt) * D_ + kc0;
            int bo = rowt * 128 + c16 * 16;
            int sw = bo ^ ((bo >> 3) & 0x70);
            cp16(bufu + OFF_BH + sw, (const char*)(g_phi + off) + c16 * 16);
            cp16(bufu + OFF_BL + sw, (const char*)(g_plo + off) + c16 * 16);
        }
        cp_commit();
    };

    int cc = 0, wc = 0;
    fill_chunk(0, 0);
    for (int kc = 0; kc < NCH; kc++) {
        if (kc < NCH - 1) {
            while (wc < cc) { mbar_wait(sbase + SM_MBAR, wc & 1); wc++; }
            fill_chunk(kc + 1, (cc + 1) & 1);
            cp_wait1();
        } else {
            cp_wait0();
        }
        fence_async();
        __syncthreads();
        if (wid == 0 && elect_one()) {
            uint32_t b0 = sbase + SM_TILES + (cc & 1) * BUF_B;
            uint64_t dAh = make_desc(b0 + OFF_AH);
            uint64_t dAl = make_desc(b0 + OFF_AL);
            uint64_t dBh = make_desc(b0 + OFF_BH);
            uint64_t dBl = make_desc(b0 + OFF_BL);
            bool first = (cc == 0);
#pragma unroll
            for (int ks = 0; ks < 4; ks++)
                mma_f16_ss(tmem, dAh + ks * 2, dBh + ks * 2, IDESC, !(first && ks == 0));
#pragma unroll
            for (int ks = 0; ks < 4; ks++)
                mma_f16_ss(tmem, dAh + ks * 2, dBl + ks * 2, IDESC, true);
#pragma unroll
            for (int ks = 0; ks < 4; ks++)
                mma_f16_ss(tmem, dAl + ks * 2, dBh + ks * 2, IDESC, true);
            mma_commit(sbase + SM_MBAR);
        }
        cc++;
    }
    while (wc < cc) { mbar_wait(sbase + SM_MBAR, wc & 1); wc++; }
    __syncthreads();
    fence_after();
    if (wid < 4) {
        float* brow = reinterpret_cast<float*>(smem + SM_TILES + (wid * 32 + lid) * BROW_B);
        uint32_t r0[32], r1[32];
#pragma unroll
        for (int g = 0; g < 3; g++) {
            LDTM_X32(r0, tmem + (2 * g) * 32);
            LDTM_X32(r1, tmem + (2 * g + 1) * 32);
            wait_ld();
#pragma unroll
            for (int j = 0; j < 32; j++)
                brow[2 * g * 32 + j]       = __uint_as_float(r0[j]);
#pragma unroll
            for (int j = 0; j < 32; j++)
                brow[(2 * g + 1) * 32 + j] = __uint_as_float(r1[j]);
        }
    }
    fence_before();
    __syncthreads();
    const float* sb = reinterpret_cast<const float*>(smem + SM_BIAS);
#pragma unroll
    for (int p = 0; p < 16; p++) {
        int rr = p * 8 + wid;
        float4 v  = *reinterpret_cast<const float4*>(smem + SM_TILES + rr * BROW_B + lid * 16);
        float4 bv = *reinterpret_cast<const float4*>(sb + lid * 4);
        v.x += bv.x; v.y += bv.y; v.z += bv.z; v.w += bv.w;
        *reinterpret_cast<float4*>(out + (size_t)(m0 + rr) * D_ + n0 + lid * 4) = v;
    }
#pragma unroll
    for (int p = 0; p < 8; p++) {
        int rr = p * 16 + wid * 2 + (lid >> 4);
        int ll = lid & 15;
        float4 v  = *reinterpret_cast<const float4*>(
            smem + SM_TILES + rr * BROW_B + 512 + ll * 16);
        float4 bv = *reinterpret_cast<const float4*>(sb + 128 + ll * 4);
        v.x += bv.x; v.y += bv.y; v.z += bv.z; v.w += bv.w;
        *reinterpret_cast<float4*>(out + (size_t)(m0 + rr) * D_ + n0 + 128 + ll * 4) = v;
    }
    __syncthreads();
    if (tid == 0) mbar_inval(sbase + SM_MBAR);
    __syncthreads();
    if (wid == 0) tmem_dealloc(tmem, 256);
#endif
}

// ===========================================================================
// SIMT fallback (bodies only when !HAS_TC) — empty on the tcgen05 target.
// ===========================================================================
__global__ void transpose_w_kernel(const float* __restrict__ conv_w) {
#if !HAS_TC
    int g = blockIdx.x * blockDim.x + threadIdx.x;
    if (g >= D_ * D_) return;
    int o = g % D_;
    int c = g / D_;
    const float* src = conv_w + ((size_t)o * D_ + c) * W_;
#pragma unroll
    for (int k = 0; k < W_; k++)
        g_Wt[((size_t)k * D_ + c) * D_ + o] = src[k];
#endif
}
__global__ void transpose_p_kernel(const float* __restrict__ proj_w) {
#if !HAS_TC
    int g = blockIdx.x * blockDim.x + threadIdx.x;
    if (g >= D_ * D_) return;
    int o = g % D_;
    int d = g / D_;
    g_Pt[(size_t)d * D_ + o] = proj_w[(size_t)o * D_ + d];
#endif
}

constexpr int KC = 16;

__global__ __launch_bounds__(256) void conv_span_kernel(const float* __restrict__ x) {
#if !HAS_TC
    __shared__ float As[KC][129];
    __shared__ float Bs[KC][128];

    const int n0 = blockIdx.x * 128;
    const int r0 = blockIdx.y * 128;
    const int b  = r0 / L_;
    const int l0 = r0 % L_;

    const int tid = threadIdx.x;
    const int tx  = tid & 15;
    const int ty  = tid >> 4;

    float acc[8][8];
#pragma unroll
    for (int i = 0; i < 8; i++)
#pragma unroll
        for (int j = 0; j < 8; j++) acc[i][j] = 0.f;

    for (int k = 0; k < W_; k++) {
        for (int kc0 = 0; kc0 < D_; kc0 += KC) {
#pragma unroll
            for (int i = 0; i < 8; i++) {
                int idx = tid + i * 256;
                int m = idx >> 4;
                int c = idx & 15;
                int t = l0 + m + k;
                As[c][m] = (t < L_) ? x[((size_t)(b * L_ + t)) * D_ + kc0 + c] : 0.f;
            }
            const float* wk = g_Wt + ((size_t)k * D_ + kc0) * D_ + n0;
#pragma unroll
            for (int i = 0; i < 8; i++) {
                int idx = tid + i * 256;
                int c = idx >> 7;
                int n = idx & 127;
                Bs[c][n] = wk[(size_t)c * D_ + n];
            }
            __syncthreads();
#pragma unroll
            for (int c = 0; c < KC; c++) {
                float a[8], bb[8];
#pragma unroll
                for (int i = 0; i < 8; i++) a[i] = As[c][ty + 16 * i];
#pragma unroll
                for (int j = 0; j < 8; j++) bb[j] = Bs[c][tx + 16 * j];
#pragma unroll
                for (int i = 0; i < 8; i++)
#pragma unroll
                    for (int j = 0; j < 8; j++)
                        acc[i][j] = fmaf(a[i], bb[j], acc[i][j]);
            }
            __syncthreads();
        }
#pragma unroll
        for (int i = 0; i < 8; i++) {
            int r = r0 + ty + 16 * i;
            float* hrow = g_H + ((size_t)r * W_ + k) * D_ + n0;
#pragma unroll
            for (int j = 0; j < 8; j++)
                hrow[tx + 16 * j] = fmaxf(acc[i][j], 0.f);
        }
    }
#endif
}

__global__ __launch_bounds__(256) void proj_kernel(const float* __restrict__ proj_b,
                                                   float* __restrict__ out) {
#if !HAS_TC
    __shared__ float As[KC][129];
    __shared__ float Bs[KC][128];

    const int n0 = blockIdx.x * 128;
    const int r0 = blockIdx.y * 128;

    const int tid = threadIdx.x;
    const int tx  = tid & 15;
    const int ty  = tid >> 4;

    float acc[8][8];
#pragma unroll
    for (int i = 0; i < 8; i++)
#pragma unroll
        for (int j = 0; j < 8; j++) acc[i][j] = 0.f;

    for (int kc0 = 0; kc0 < D_; kc0 += KC) {
#pragma unroll
        for (int i = 0; i < 8; i++) {
            int idx = tid + i * 256;
            int m = idx >> 4;
            int c = idx & 15;
            As[c][m] = g_H[(size_t)(r0 + m) * D_ + kc0 + c];
        }
#pragma unroll
        for (int i = 0; i < 8; i++) {
            int idx = tid + i * 256;
            int c = idx >> 7;
            int n = idx & 127;
            Bs[c][n] = g_Pt[(size_t)(kc0 + c) * D_ + n0 + n];
        }
        __syncthreads();
#pragma unroll
        for (int c = 0; c < KC; c++) {
            float a[8], bb[8];
#pragma unroll
            for (int i = 0; i < 8; i++) a[i] = As[c][ty + 16 * i];
#pragma unroll
            for (int j = 0; j < 8; j++) bb[j] = Bs[c][tx + 16 * j];
#pragma unroll
            for (int i = 0; i < 8; i++)
#pragma unroll
                for (int j = 0; j < 8; j++)
                    acc[i][j] = fmaf(a[i], bb[j], acc[i][j]);
        }
        __syncthreads();
    }

    float bias[8];
#pragma unroll
    for (int j = 0; j < 8; j++) bias[j] = proj_b[n0 + tx + 16 * j];

#pragma unroll
    for (int i = 0; i < 8; i++) {
        size_t r = (size_t)(r0 + ty + 16 * i);
#pragma unroll
        for (int j = 0; j < 8; j++)
            out[r * D_ + n0 + tx + 16 * j] = acc[i][j] + bias[j];
    }
#endif
}

// ===========================================================================
extern "C" void kernel_launch(void* const* d_in, const int* in_sizes, int n_in,
                              void* d_out, int out_size) {
    const float* x      = (const float*)d_in[0];
    const float* conv_w = (const float*)d_in[1];
    const float* proj_w = (const float*)d_in[2];
    const float* proj_b = (const float*)d_in[3];
    float* out = (float*)d_out;
    (void)in_sizes; (void)n_in; (void)out_size;

    // --- SIMT path FIRST (proven launch order; empty kernels on the tcgen05
    //     target). ---
    const int tp_blocks = (D_ * D_ + 255) / 256;
    transpose_w_kernel<<<tp_blocks, 256>>>(conv_w);
    transpose_p_kernel<<<tp_blocks, 256>>>(proj_w);
    conv_span_kernel<<<dim3(D_ / 128, NROW / 128), 256>>>(x);
    proj_kernel<<<dim3(D_ / 128, MROW2 / 128), 256>>>(proj_b, out);

    // --- tcgen05 path (empty kernels when only base sm_103 is compiled) ---
    cudaFuncSetAttribute(conv_mma_kernel, cudaFuncAttributeMaxDynamicSharedMemorySize, SMEM_SZ);
    cudaFuncSetAttribute(proj_mma_kernel, cudaFuncAttributeMaxDynamicSharedMemorySize, SMEM_SZ);

    split_x_kernel<<<(NROW * D_ + 255) / 256, 256>>>(x);
    split_w_kernel<<<(D_ * D_ + 255) / 256, 256>>>(conv_w);
    split_p_kernel<<<(D_ * D_ + 255) / 256, 256>>>(proj_w);

    conv_mma_kernel<<<dim3(D_ / NT, NROW / 128), 256, SMEM_SZ>>>();
    proj_mma_kernel<<<dim3(D_ / NT, MROW2 / 128), 256, SMEM_SZ>>>(proj_b, out);
}

// round 16
// speedup vs baseline: 1.0351x; 1.0351x over previous
#include <cuda_runtime.h>
#include <cuda_bf16.h>
#include <cstdint>

// ---------------------------------------------------------------------------
// Arch feature gate: tcgen05 only on arch/family-specific sm_10x targets.
// ---------------------------------------------------------------------------
#if defined(__CUDA_ARCH__)
#  if defined(__CUDA_ARCH_FEAT_SM103_ALL) || defined(__CUDA_ARCH_FEAT_SM100_ALL)
#    define HAS_TC 1
#  elif defined(__CUDA_ARCH_SPECIFIC__) && (__CUDA_ARCH_SPECIFIC__ == 1030 || __CUDA_ARCH_SPECIFIC__ == 1000)
#    define HAS_TC 1
#  elif defined(__CUDA_ARCH_FAMILY_SPECIFIC__) && (__CUDA_ARCH_FAMILY_SPECIFIC__ == 1030 || __CUDA_ARCH_FAMILY_SPECIFIC__ == 1000)
#    define HAS_TC 1
#  else
#    define HAS_TC 0
#  endif
#else
#  define HAS_TC 0
#endif

#define B_ 8
#define L_ 512
#define D_ 768
#define W_ 12

constexpr int NROW  = B_ * L_;       // 4096
constexpr int MROW2 = NROW * W_;     // 49152
constexpr int CH    = 64;            // K-chunk (bf16) = 128B rows (SW128)
constexpr int NCH   = D_ / CH;       // 12
constexpr int NT    = 192;           // N per CTA (one MMA, N=192)

// ---- SMEM map (tc kernels): 2-stage, N=192 tiles (proven 164864B) ----
constexpr int SM_TMEM  = 0;
constexpr int SM_MBAR  = 8;
constexpr int SM_BIAS  = 256;                  // 192 floats (proj)
constexpr int SM_TILES = 1024;
constexpr int TILE_A   = 128 * 128;            // 16 KB  (A: 128 rows x 128B)
constexpr int TILE_BN  = NT * 128;             // 24576 (B: 192 rows x 128B)
constexpr int OFF_AH   = 0;
constexpr int OFF_AL   = TILE_A;
constexpr int OFF_BH   = 2 * TILE_A;
constexpr int OFF_BL   = 2 * TILE_A + TILE_BN;
constexpr int BUF_B    = 2 * TILE_A + 2 * TILE_BN;   // 81920
constexpr int SMEM_SZ  = SM_TILES + 2 * BUF_B;       // 164864 (< hang zone)
constexpr int BROW_B   = 784;                  // bounce row pitch (768B + 16B pad)

// idesc kind::f16 : dtype=F32, a=BF16, b=BF16, N=192, M=128
constexpr uint32_t IDESC =
    (1u << 4) | (1u << 7) | (1u << 10) | ((uint32_t)(NT / 8) << 17) | ((128u / 16) << 24);

// ---- scratch ----
__device__ __nv_bfloat16 g_xhi[(size_t)NROW * D_],   g_xlo[(size_t)NROW * D_];
__device__ __nv_bfloat16 g_whi[(size_t)W_ * D_ * D_], g_wlo[(size_t)W_ * D_ * D_]; // [k][o][c]
__device__ __nv_bfloat16 g_phi[(size_t)D_ * D_],     g_plo[(size_t)D_ * D_];       // [o][d]
__device__ __nv_bfloat16 g_hhi[(size_t)MROW2 * D_],  g_hlo[(size_t)MROW2 * D_];
// SIMT fallback scratch
__device__ float g_Wt[(size_t)W_ * D_ * D_];
__device__ float g_Pt[(size_t)D_ * D_];
__device__ float g_H [(size_t)MROW2 * D_];

// ===========================================================================
// helpers
// ===========================================================================
__device__ __forceinline__ uint32_t smem_u32(const void* p) {
    uint32_t a;
    asm("{ .reg .u64 t; cvta.to.shared.u64 t, %1; cvt.u32.u64 %0, t; }" : "=r"(a) : "l"(p));
    return a;
}
__device__ __forceinline__ void split2(float v, __nv_bfloat16& hi, __nv_bfloat16& lo) {
    hi = __float2bfloat16(v);
    lo = __float2bfloat16(v - __bfloat162float(hi));
}

#if HAS_TC
__device__ __forceinline__ uint32_t elect_one() {
    uint32_t p;
    asm volatile("{ .reg .pred p; elect.sync _|p, 0xFFFFFFFF; selp.b32 %0, 1, 0, p; }" : "=r"(p));
    return p;
}
__device__ __forceinline__ void mbar_init(uint32_t m, uint32_t cnt) {
    asm volatile("mbarrier.init.shared.b64 [%0], %1;" :: "r"(m), "r"(cnt) : "memory");
}
__device__ __forceinline__ void mbar_inval(uint32_t m) {
    asm volatile("mbarrier.inval.shared.b64 [%0];" :: "r"(m) : "memory");
}
__device__ __forceinline__ void mbar_wait(uint32_t m, uint32_t parity) {
    asm volatile(
        "{\n\t.reg .pred P;\n\t"
        "WL_%=:\n\t"
        "mbarrier.try_wait.parity.acquire.cta.shared::cta.b64 P, [%0], %1, 0x989680;\n\t"
        "@P bra.uni WD_%=;\n\t"
        "bra.uni WL_%=;\n\t"
        "WD_%=:\n\t}"
        :: "r"(m), "r"(parity) : "memory");
}
__device__ __forceinline__ void tmem_alloc(uint32_t smem_dst, uint32_t ncols) {
    asm volatile("tcgen05.alloc.cta_group::1.sync.aligned.shared::cta.b32 [%0], %1;"
                 :: "r"(smem_dst), "r"(ncols) : "memory");
}
__device__ __forceinline__ void tmem_dealloc(uint32_t tmem, uint32_t ncols) {
    asm volatile("tcgen05.relinquish_alloc_permit.cta_group::1.sync.aligned;");
    asm volatile("tcgen05.dealloc.cta_group::1.sync.aligned.b32 %0, %1;" :: "r"(tmem), "r"(ncols));
}
__device__ __forceinline__ void mma_commit(uint32_t mbar) {
    asm volatile("tcgen05.commit.cta_group::1.mbarrier::arrive::one.shared::cluster.b64 [%0];"
                 :: "r"(mbar) : "memory");
}
__device__ __forceinline__ void fence_after()  { asm volatile("tcgen05.fence::after_thread_sync;"  ::: "memory"); }
__device__ __forceinline__ void fence_before() { asm volatile("tcgen05.fence::before_thread_sync;" ::: "memory"); }
__device__ __forceinline__ void wait_ld()      { asm volatile("tcgen05.wait::ld.sync.aligned;"     ::: "memory"); }
__device__ __forceinline__ void fence_async()  { asm volatile("fence.proxy.async.shared::cta;"     ::: "memory"); }

// cp.async 16B copy (sm_80+): plain and zero-fill-predicated forms.
__device__ __forceinline__ void cp16(uint32_t dst, const void* src) {
    asm volatile("cp.async.cg.shared.global [%0], [%1], 16;"
                 :: "r"(dst), "l"(src) : "memory");
}
__device__ __forceinline__ void cp16z(uint32_t dst, const void* src, int src_size) {
    asm volatile("cp.async.cg.shared.global [%0], [%1], 16, %2;"
                 :: "r"(dst), "l"(src), "r"(src_size) : "memory");
}
__device__ __forceinline__ void cp_commit() {
    asm volatile("cp.async.commit_group;" ::: "memory");
}
__device__ __forceinline__ void cp_wait0() {
    asm volatile("cp.async.wait_group 0;" ::: "memory");
}
__device__ __forceinline__ void cp_wait1() {
    asm volatile("cp.async.wait_group 1;" ::: "memory");
}

__device__ __forceinline__ void mma_f16_ss(uint32_t d_tmem, uint64_t a_desc, uint64_t b_desc,
                                           uint32_t idesc, bool acc) {
    uint32_t en = acc ? 1u : 0u;
    uint32_t z = 0;
    asm volatile(
        "{\n\t.reg .pred p;\n\tsetp.ne.u32 p, %5, 0;\n\t"
        "tcgen05.mma.cta_group::1.kind::f16 [%0], %1, %2, %3, {%4, %4, %4, %4}, p;\n\t}"
        :: "r"(d_tmem), "l"(a_desc), "l"(b_desc), "r"(idesc), "r"(z), "r"(en) : "memory");
}
__device__ __forceinline__ uint64_t make_desc(uint32_t addr) {
    constexpr uint64_t BASE =
        (uint64_t(2) << 61) | (uint64_t(1) << 46) | (uint64_t(64) << 32) | (uint64_t(1) << 16);
    return BASE | ((uint64_t)(addr >> 4) & 0x3FFF);
}
#define LDTM_X32(r, a)                                                              \
    asm volatile("tcgen05.ld.sync.aligned.32x32b.x32.b32 "                          \
        "{%0, %1, %2, %3, %4, %5, %6, %7, %8, %9, %10, %11, %12, %13, %14, %15, "   \
        " %16, %17, %18, %19, %20, %21, %22, %23, %24, %25, %26, %27, %28, %29, %30, %31}, [%32];" \
        : "=r"((r)[0]), "=r"((r)[1]), "=r"((r)[2]), "=r"((r)[3]),                   \
          "=r"((r)[4]), "=r"((r)[5]), "=r"((r)[6]), "=r"((r)[7]),                   \
          "=r"((r)[8]), "=r"((r)[9]), "=r"((r)[10]), "=r"((r)[11]),                 \
          "=r"((r)[12]), "=r"((r)[13]), "=r"((r)[14]), "=r"((r)[15]),               \
          "=r"((r)[16]), "=r"((r)[17]), "=r"((r)[18]), "=r"((r)[19]),               \
          "=r"((r)[20]), "=r"((r)[21]), "=r"((r)[22]), "=r"((r)[23]),               \
          "=r"((r)[24]), "=r"((r)[25]), "=r"((r)[26]), "=r"((r)[27]),               \
          "=r"((r)[28]), "=r"((r)[29]), "=r"((r)[30]), "=r"((r)[31])                \
        : "r"(a))
#endif // HAS_TC

// ===========================================================================
// tc-path prep kernels
// ===========================================================================
__global__ void split_x_kernel(const float* __restrict__ x) {
#if HAS_TC
    int g = blockIdx.x * 256 + threadIdx.x;
    if (g >= NROW * D_) return;
    __nv_bfloat16 h, l;
    split2(x[g], h, l);
    g_xhi[g] = h; g_xlo[g] = l;
#endif
}
__global__ void split_w_kernel(const float* __restrict__ cw) {  // [o][c][k] -> [k][o][c]
#if HAS_TC
    int g = blockIdx.x * 256 + threadIdx.x;
    if (g >= D_ * D_) return;
    int c = g % D_, o = g / D_;
    const float* src = cw + ((size_t)o * D_ + c) * W_;
#pragma unroll
    for (int k = 0; k < W_; k++) {
        __nv_bfloat16 h, l;
        split2(src[k], h, l);
        size_t dst = ((size_t)k * D_ + o) * D_ + c;
        g_whi[dst] = h; g_wlo[dst] = l;
    }
#endif
}
__global__ void split_p_kernel(const float* __restrict__ pw) {
#if HAS_TC
    int g = blockIdx.x * 256 + threadIdx.x;
    if (g >= D_ * D_) return;
    __nv_bfloat16 h, l;
    split2(pw[g], h, l);
    g_phi[g] = h; g_plo[g] = l;
#endif
}

// ===========================================================================
// tc Kernel 1: taps GEMM (M=128 x N=192 per CTA), cumsum in TMEM.
// 256 threads. Within-tap one-chunk-ahead cp.async prefetch (wait_group 1);
// no fill is in flight across a tap boundary. (R14-proven 423.7us version.)
// ===========================================================================
__global__ __launch_bounds__(256, 1) void conv_mma_kernel() {
#if HAS_TC
    extern __shared__ char smem[];
    const uint32_t sbase = smem_u32(smem);
    const int tid = threadIdx.x;
    const int wid = tid >> 5, lid = tid & 31;

    if (wid == 0) tmem_alloc(sbase + SM_TMEM, 256);
    if (tid == 0) mbar_init(sbase + SM_MBAR, 1);
    __syncthreads();
    uint32_t tmem;
    asm volatile("ld.shared.b32 %0, [%1];" : "=r"(tmem) : "r"(sbase + SM_TMEM));

    const int n0 = blockIdx.x * NT;
    const int m0 = blockIdx.y * 128;
    const int bb = m0 / L_;
    const int l0 = m0 % L_;

    auto fill_chunk = [&](int k, int kc, int b) {
        const int kc0 = kc * CH;
        const uint32_t bufu = sbase + SM_TILES + b * BUF_B;
#pragma unroll
        for (int it = 0; it < 4; it++) {                   // A tiles (shifted rows)
            int idx = it * 256 + tid;
            int rowt = idx >> 3, c16 = idx & 7;
            int t = l0 + rowt + k;
            int tcl = t < L_ ? t : (L_ - 1);
            int pr  = t < L_ ? 16 : 0;
            size_t off = ((size_t)(bb * L_ + tcl)) * D_ + kc0;
            int bo = rowt * 128 + c16 * 16;
            int sw = bo ^ ((bo >> 3) & 0x70);
            cp16z(bufu + OFF_AH + sw, (const char*)(g_xhi + off) + c16 * 16, pr);
            cp16z(bufu + OFF_AL + sw, (const char*)(g_xlo + off) + c16 * 16, pr);
        }
#pragma unroll
        for (int it = 0; it < 6; it++) {                   // B tiles (192 rows, tap k)
            int idx = it * 256 + tid;
            int rowt = idx >> 3, c16 = idx & 7;
            size_t off = ((size_t)k * D_ + (n0 + rowt)) * D_ + kc0;
            int bo = rowt * 128 + c16 * 16;
            int sw = bo ^ ((bo >> 3) & 0x70);
            cp16(bufu + OFF_BH + sw, (const char*)(g_whi + off) + c16 * 16);
            cp16(bufu + OFF_BL + sw, (const char*)(g_wlo + off) + c16 * 16);
        }
        cp_commit();
    };

    int cc = 0, wc = 0;
    for (int k = 0; k < W_; k++) {
        // tap prologue: both buffers idle (previous tap fully drained)
        fill_chunk(k, 0, cc & 1);
        for (int kc = 0; kc < NCH; kc++) {
            if (kc < NCH - 1) {
                // buffer (cc+1)&1 was read by MMA(cc-1): wait it, then prefetch
                while (wc < cc) { mbar_wait(sbase + SM_MBAR, wc & 1); wc++; }
                fill_chunk(k, kc + 1, (cc + 1) & 1);
                cp_wait1();                                 // fill(cc) complete
            } else {
                cp_wait0();                                 // last chunk of tap
            }
            fence_async();
            __syncthreads();
            if (wid == 0 && elect_one()) {
                uint32_t b0 = sbase + SM_TILES + (cc & 1) * BUF_B;
                uint64_t dAh = make_desc(b0 + OFF_AH);
                uint64_t dAl = make_desc(b0 + OFF_AL);
                uint64_t dBh = make_desc(b0 + OFF_BH);
                uint64_t dBl = make_desc(b0 + OFF_BL);
                bool first = (cc == 0);
#pragma unroll
                for (int ks = 0; ks < 4; ks++)
                    mma_f16_ss(tmem, dAh + ks * 2, dBh + ks * 2, IDESC, !(first && ks == 0));
#pragma unroll
                for (int ks = 0; ks < 4; ks++)
                    mma_f16_ss(tmem, dAh + ks * 2, dBl + ks * 2, IDESC, true);
#pragma unroll
                for (int ks = 0; ks < 4; ks++)
                    mma_f16_ss(tmem, dAl + ks * 2, dBh + ks * 2, IDESC, true);
                mma_commit(sbase + SM_MBAR);
            }
            cc++;
        }
        while (wc < cc) { mbar_wait(sbase + SM_MBAR, wc & 1); wc++; }   // drain tap
        __syncthreads();
        fence_after();
        // ---- epilogue 1: LDTM (192 cols, warps 0-3 only) -> relu -> bounce ----
        if (wid < 4) {
            float* brow = reinterpret_cast<float*>(smem + SM_TILES + (wid * 32 + lid) * BROW_B);
            uint32_t r0[32], r1[32];
#pragma unroll
            for (int g = 0; g < 3; g++) {
                LDTM_X32(r0, tmem + (2 * g) * 32);
                LDTM_X32(r1, tmem + (2 * g + 1) * 32);
                wait_ld();
#pragma unroll
                for (int j = 0; j < 32; j++)
                    brow[2 * g * 32 + j]       = fmaxf(__uint_as_float(r0[j]), 0.f);
#pragma unroll
                for (int j = 0; j < 32; j++)
                    brow[(2 * g + 1) * 32 + j] = fmaxf(__uint_as_float(r1[j]), 0.f);
            }
        }
        fence_before();
        __syncthreads();
        // ---- epilogue 2a: cols 0..127, 8 warps coalesced split + store ----
#pragma unroll
        for (int p = 0; p < 16; p++) {
            int rr = p * 8 + wid;
            float4 v = *reinterpret_cast<const float4*>(smem + SM_TILES + rr * BROW_B + lid * 16);
            __nv_bfloat16 h0, q0, h1, q1, h2, q2, h3, q3;
            split2(v.x, h0, q0); split2(v.y, h1, q1);
            split2(v.z, h2, q2); split2(v.w, h3, q3);
            __nv_bfloat162 ph0, ph1, pl0, pl1;
            ph0.x = h0; ph0.y = h1; ph1.x = h2; ph1.y = h3;
            pl0.x = q0; pl0.y = q1; pl1.x = q2; pl1.y = q3;
            size_t base = ((size_t)(m0 + rr) * W_ + k) * D_ + n0 + lid * 4;
            uint2 uh = make_uint2(*reinterpret_cast<uint32_t*>(&ph0),
                                  *reinterpret_cast<uint32_t*>(&ph1));
            uint2 ul = make_uint2(*reinterpret_cast<uint32_t*>(&pl0),
                                  *reinterpret_cast<uint32_t*>(&pl1));
            *reinterpret_cast<uint2*>(g_hhi + base) = uh;
            *reinterpret_cast<uint2*>(g_hlo + base) = ul;
        }
        // ---- epilogue 2b: cols 128..191 (8 warps, half-warp per row) ----
#pragma unroll
        for (int p = 0; p < 8; p++) {
            int rr = p * 16 + wid * 2 + (lid >> 4);
            int ll = lid & 15;
            float4 v = *reinterpret_cast<const float4*>(
                smem + SM_TILES + rr * BROW_B + 512 + ll * 16);
            __nv_bfloat16 h0, q0, h1, q1, h2, q2, h3, q3;
            split2(v.x, h0, q0); split2(v.y, h1, q1);
            split2(v.z, h2, q2); split2(v.w, h3, q3);
            __nv_bfloat162 ph0, ph1, pl0, pl1;
            ph0.x = h0; ph0.y = h1; ph1.x = h2; ph1.y = h3;
            pl0.x = q0; pl0.y = q1; pl1.x = q2; pl1.y = q3;
            size_t base = ((size_t)(m0 + rr) * W_ + k) * D_ + n0 + 128 + ll * 4;
            uint2 uh = make_uint2(*reinterpret_cast<uint32_t*>(&ph0),
                                  *reinterpret_cast<uint32_t*>(&ph1));
            uint2 ul = make_uint2(*reinterpret_cast<uint32_t*>(&pl0),
                                  *reinterpret_cast<uint32_t*>(&pl1));
            *reinterpret_cast<uint2*>(g_hhi + base) = uh;
            *reinterpret_cast<uint2*>(g_hlo + base) = ul;
        }
        __syncthreads();
    }
    __syncthreads();
    if (tid == 0) mbar_inval(sbase + SM_MBAR);
    __syncthreads();
    if (wid == 0) tmem_dealloc(tmem, 256);
#endif
}

// ===========================================================================
// tc Kernel 2: out = H @ projT + bias (M=128 x N=192 per CTA). 256 threads.
// (R14-proven version.)
// ===========================================================================
__global__ __launch_bounds__(256, 1) void proj_mma_kernel(const float* __restrict__ proj_b,
                                                          float* __restrict__ out) {
#if HAS_TC
    extern __shared__ char smem[];
    const uint32_t sbase = smem_u32(smem);
    const int tid = threadIdx.x;
    const int wid = tid >> 5, lid = tid & 31;

    if (wid == 0) tmem_alloc(sbase + SM_TMEM, 256);
    if (tid == 0) mbar_init(sbase + SM_MBAR, 1);
    const int n0 = blockIdx.x * NT;
    const int m0 = blockIdx.y * 128;
    if (tid < 192) reinterpret_cast<float*>(smem + SM_BIAS)[tid] = proj_b[n0 + tid];
    __syncthreads();
    uint32_t tmem;
    asm volatile("ld.shared.b32 %0, [%1];" : "=r"(tmem) : "r"(sbase + SM_TMEM));

    auto fill_chunk = [&](int kc, int b) {
        const int kc0 = kc * CH;
        const uint32_t bufu = sbase + SM_TILES + b * BUF_B;
#pragma unroll
        for (int it = 0; it < 4; it++) {
            int idx = it * 256 + tid;
            int rowt = idx >> 3, c16 = idx & 7;
            size_t off = (size_t)(m0 + rowt) * D_ + kc0;
            int bo = rowt * 128 + c16 * 16;
            int sw = bo ^ ((bo >> 3) & 0x70);
            cp16(bufu + OFF_AH + sw, (const char*)(g_hhi + off) + c16 * 16);
            cp16(bufu + OFF_AL + sw, (const char*)(g_hlo + off) + c16 * 16);
        }
#pragma unroll
        for (int it = 0; it < 6; it++) {
            int idx = it * 256 + tid;
            int rowt = idx >> 3, c16 = idx & 7;
            size_t off = (size_t)(n0 + rowt) * D_ + kc0;
            int bo = rowt * 128 + c16 * 16;
            int sw = bo ^ ((bo >> 3) & 0x70);
            cp16(bufu + OFF_BH + sw, (const char*)(g_phi + off) + c16 * 16);
            cp16(bufu + OFF_BL + sw, (const char*)(g_plo + off) + c16 * 16);
        }
        cp_commit();
    };

    int cc = 0, wc = 0;
    fill_chunk(0, 0);
    for (int kc = 0; kc < NCH; kc++) {
        if (kc < NCH - 1) {
            while (wc < cc) { mbar_wait(sbase + SM_MBAR, wc & 1); wc++; }
            fill_chunk(kc + 1, (cc + 1) & 1);
            cp_wait1();
        } else {
            cp_wait0();
        }
        fence_async();
        __syncthreads();
        if (wid == 0 && elect_one()) {
            uint32_t b0 = sbase + SM_TILES + (cc & 1) * BUF_B;
            uint64_t dAh = make_desc(b0 + OFF_AH);
            uint64_t dAl = make_desc(b0 + OFF_AL);
            uint64_t dBh = make_desc(b0 + OFF_BH);
            uint64_t dBl = make_desc(b0 + OFF_BL);
            bool first = (cc == 0);
#pragma unroll
            for (int ks = 0; ks < 4; ks++)
                mma_f16_ss(tmem, dAh + ks * 2, dBh + ks * 2, IDESC, !(first && ks == 0));
#pragma unroll
            for (int ks = 0; ks < 4; ks++)
                mma_f16_ss(tmem, dAh + ks * 2, dBl + ks * 2, IDESC, true);
#pragma unroll
            for (int ks = 0; ks < 4; ks++)
                mma_f16_ss(tmem, dAl + ks * 2, dBh + ks * 2, IDESC, true);
            mma_commit(sbase + SM_MBAR);
        }
        cc++;
    }
    while (wc < cc) { mbar_wait(sbase + SM_MBAR, wc & 1); wc++; }
    __syncthreads();
    fence_after();
    // ---- epilogue: LDTM (warps 0-3) -> bounce -> 8-warp bias add + store ----
    if (wid < 4) {
        float* brow = reinterpret_cast<float*>(smem + SM_TILES + (wid * 32 + lid) * BROW_B);
        uint32_t r0[32], r1[32];
#pragma unroll
        for (int g = 0; g < 3; g++) {
            LDTM_X32(r0, tmem + (2 * g) * 32);
            LDTM_X32(r1, tmem + (2 * g + 1) * 32);
            wait_ld();
#pragma unroll
            for (int j = 0; j < 32; j++)
                brow[2 * g * 32 + j]       = __uint_as_float(r0[j]);
#pragma unroll
            for (int j = 0; j < 32; j++)
                brow[(2 * g + 1) * 32 + j] = __uint_as_float(r1[j]);
        }
    }
    fence_before();
    __syncthreads();
    const float* sb = reinterpret_cast<const float*>(smem + SM_BIAS);
#pragma unroll
    for (int p = 0; p < 16; p++) {
        int rr = p * 8 + wid;
        float4 v  = *reinterpret_cast<const float4*>(smem + SM_TILES + rr * BROW_B + lid * 16);
        float4 bv = *reinterpret_cast<const float4*>(sb + lid * 4);
        v.x += bv.x; v.y += bv.y; v.z += bv.z; v.w += bv.w;
        *reinterpret_cast<float4*>(out + (size_t)(m0 + rr) * D_ + n0 + lid * 4) = v;
    }
#pragma unroll
    for (int p = 0; p < 8; p++) {
        int rr = p * 16 + wid * 2 + (lid >> 4);
        int ll = lid & 15;
        float4 v  = *reinterpret_cast<const float4*>(
            smem + SM_TILES + rr * BROW_B + 512 + ll * 16);
        float4 bv = *reinterpret_cast<const float4*>(sb + 128 + ll * 4);
        v.x += bv.x; v.y += bv.y; v.z += bv.z; v.w += bv.w;
        *reinterpret_cast<float4*>(out + (size_t)(m0 + rr) * D_ + n0 + 128 + ll * 4) = v;
    }
    __syncthreads();
    if (tid == 0) mbar_inval(sbase + SM_MBAR);
    __syncthreads();
    if (wid == 0) tmem_dealloc(tmem, 256);
#endif
}

// ===========================================================================
// SIMT fallback (bodies only when !HAS_TC) — empty on the tcgen05 target.
// ===========================================================================
__global__ void transpose_w_kernel(const float* __restrict__ conv_w) {
#if !HAS_TC
    int g = blockIdx.x * blockDim.x + threadIdx.x;
    if (g >= D_ * D_) return;
    int o = g % D_;
    int c = g / D_;
    const float* src = conv_w + ((size_t)o * D_ + c) * W_;
#pragma unroll
    for (int k = 0; k < W_; k++)
        g_Wt[((size_t)k * D_ + c) * D_ + o] = src[k];
#endif
}
__global__ void transpose_p_kernel(const float* __restrict__ proj_w) {
#if !HAS_TC
    int g = blockIdx.x * blockDim.x + threadIdx.x;
    if (g >= D_ * D_) return;
    int o = g % D_;
    int d = g / D_;
    g_Pt[(size_t)d * D_ + o] = proj_w[(size_t)o * D_ + d];
#endif
}

constexpr int KC = 16;

__global__ __launch_bounds__(256) void conv_span_kernel(const float* __restrict__ x) {
#if !HAS_TC
    __shared__ float As[KC][129];
    __shared__ float Bs[KC][128];

    const int n0 = blockIdx.x * 128;
    const int r0 = blockIdx.y * 128;
    const int b  = r0 / L_;
    const int l0 = r0 % L_;

    const int tid = threadIdx.x;
    const int tx  = tid & 15;
    const int ty  = tid >> 4;

    float acc[8][8];
#pragma unroll
    for (int i = 0; i < 8; i++)
#pragma unroll
        for (int j = 0; j < 8; j++) acc[i][j] = 0.f;

    for (int k = 0; k < W_; k++) {
        for (int kc0 = 0; kc0 < D_; kc0 += KC) {
#pragma unroll
            for (int i = 0; i < 8; i++) {
                int idx = tid + i * 256;
                int m = idx >> 4;
                int c = idx & 15;
                int t = l0 + m + k;
                As[c][m] = (t < L_) ? x[((size_t)(b * L_ + t)) * D_ + kc0 + c] : 0.f;
            }
            const float* wk = g_Wt + ((size_t)k * D_ + kc0) * D_ + n0;
#pragma unroll
            for (int i = 0; i < 8; i++) {
                int idx = tid + i * 256;
                int c = idx >> 7;
                int n = idx & 127;
                Bs[c][n] = wk[(size_t)c * D_ + n];
            }
            __syncthreads();
#pragma unroll
            for (int c = 0; c < KC; c++) {
                float a[8], bb[8];
#pragma unroll
                for (int i = 0; i < 8; i++) a[i] = As[c][ty + 16 * i];
#pragma unroll
                for (int j = 0; j < 8; j++) bb[j] = Bs[c][tx + 16 * j];
#pragma unroll
                for (int i = 0; i < 8; i++)
#pragma unroll
                    for (int j = 0; j < 8; j++)
                        acc[i][j] = fmaf(a[i], bb[j], acc[i][j]);
            }
            __syncthreads();
        }
#pragma unroll
        for (int i = 0; i < 8; i++) {
            int r = r0 + ty + 16 * i;
            float* hrow = g_H + ((size_t)r * W_ + k) * D_ + n0;
#pragma unroll
            for (int j = 0; j < 8; j++)
                hrow[tx + 16 * j] = fmaxf(acc[i][j], 0.f);
        }
    }
#endif
}

__global__ __launch_bounds__(256) void proj_kernel(const float* __restrict__ proj_b,
                                                   float* __restrict__ out) {
#if !HAS_TC
    __shared__ float As[KC][129];
    __shared__ float Bs[KC][128];

    const int n0 = blockIdx.x * 128;
    const int r0 = blockIdx.y * 128;

    const int tid = threadIdx.x;
    const int tx  = tid & 15;
    const int ty  = tid >> 4;

    float acc[8][8];
#pragma unroll
    for (int i = 0; i < 8; i++)
#pragma unroll
        for (int j = 0; j < 8; j++) acc[i][j] = 0.f;

    for (int kc0 = 0; kc0 < D_; kc0 += KC) {
#pragma unroll
        for (int i = 0; i < 8; i++) {
            int idx = tid + i * 256;
            int m = idx >> 4;
            int c = idx & 15;
            As[c][m] = g_H[(size_t)(r0 + m) * D_ + kc0 + c];
        }
#pragma unroll
        for (int i = 0; i < 8; i++) {
            int idx = tid + i * 256;
            int c = idx >> 7;
            int n = idx & 127;
            Bs[c][n] = g_Pt[(size_t)(kc0 + c) * D_ + n0 + n];
        }
        __syncthreads();
#pragma unroll
        for (int c = 0; c < KC; c++) {
            float a[8], bb[8];
#pragma unroll
            for (int i = 0; i < 8; i++) a[i] = As[c][ty + 16 * i];
#pragma unroll
            for (int j = 0; j < 8; j++) bb[j] = Bs[c][tx + 16 * j];
#pragma unroll
            for (int i = 0; i < 8; i++)
#pragma unroll
                for (int j = 0; j < 8; j++)
                    acc[i][j] = fmaf(a[i], bb[j], acc[i][j]);
        }
        __syncthreads();
    }

    float bias[8];
#pragma unroll
    for (int j = 0; j < 8; j++) bias[j] = proj_b[n0 + tx + 16 * j];

#pragma unroll
    for (int i = 0; i < 8; i++) {
        size_t r = (size_t)(r0 + ty + 16 * i);
#pragma unroll
        for (int j = 0; j < 8; j++)
            out[r * D_ + n0 + tx + 16 * j] = acc[i][j] + bias[j];
    }
#endif
}

// ===========================================================================
extern "C" void kernel_launch(void* const* d_in, const int* in_sizes, int n_in,
                              void* d_out, int out_size) {
    const float* x      = (const float*)d_in[0];
    const float* conv_w = (const float*)d_in[1];
    const float* proj_w = (const float*)d_in[2];
    const float* proj_b = (const float*)d_in[3];
    float* out = (float*)d_out;
    (void)in_sizes; (void)n_in; (void)out_size;

    // Which path is live in this build? The dead path's kernels compile to
    // empty bodies (~16 regs); the live tcgen05 conv_mma needs >=40 regs.
    // cudaFuncGetAttributes is host-side (capture-safe, deterministic).
    cudaFuncAttributes fa{};
    bool tc = false;
    if (cudaFuncGetAttributes(&fa, (const void*)conv_mma_kernel) == cudaSuccess)
        tc = (fa.numRegs >= 40);

    // --- SIMT path FIRST (launch order preserved; dead kernels get a 1-block
    //     grid so their launches stay as cheap placeholders for the ncu slots) ---
    const int tp_blocks = (D_ * D_ + 255) / 256;
    dim3 g_tp   = tc ? dim3(1, 1) : dim3(tp_blocks);
    dim3 g_conv = tc ? dim3(1, 1) : dim3(D_ / 128, NROW / 128);
    dim3 g_proj = tc ? dim3(1, 1) : dim3(D_ / 128, MROW2 / 128);
    transpose_w_kernel<<<g_tp, 256>>>(conv_w);
    transpose_p_kernel<<<g_tp, 256>>>(proj_w);
    conv_span_kernel<<<g_conv, 256>>>(x);
    proj_kernel<<<g_proj, 256>>>(proj_b, out);

    // --- tcgen05 path (1-block placeholders when only base sm_103 is live) ---
    cudaFuncSetAttribute(conv_mma_kernel, cudaFuncAttributeMaxDynamicSharedMemorySize, SMEM_SZ);
    cudaFuncSetAttribute(proj_mma_kernel, cudaFuncAttributeMaxDynamicSharedMemorySize, SMEM_SZ);

    dim3 g_sx = tc ? dim3((NROW * D_ + 255) / 256) : dim3(1);
    dim3 g_sw = tc ? dim3((D_ * D_ + 255) / 256)   : dim3(1);
    dim3 g_cm = tc ? dim3(D_ / NT, NROW / 128)     : dim3(1, 1);
    dim3 g_pm = tc ? dim3(D_ / NT, MROW2 / 128)    : dim3(1, 1);

    split_x_kernel<<<g_sx, 256>>>(x);
    split_w_kernel<<<g_sw, 256>>>(conv_w);
    split_p_kernel<<<g_sw, 256>>>(proj_w);

    conv_mma_kernel<<<g_cm, 256, SMEM_SZ>>>();
    proj_mma_kernel<<<g_pm, 256, SMEM_SZ>>>(proj_b, out);
}